// round 1
// baseline (speedup 1.0000x reference)
#include <cuda_runtime.h>
#include <float.h>

#define BATCH 8
#define C 512
#define HW 16384
#define KCLS 150

// ---------------- scratch (device globals; no allocations) ----------------
__device__ float g_CA[BATCH * KCLS * HW];     // coupled_attn, later reused for raw masks
__device__ float g_af[BATCH * C * HW];        // aligned_feat stored transposed [b,c,n]
__device__ float g_pool[BATCH * KCLS * C];
__device__ float g_acls[BATCH * KCLS * C];
__device__ float g_clsWf[KCLS * C];           // cls_repr @ W_feat^T
__device__ float g_rowmax[BATCH * KCLS];
__device__ float g_rowsum[BATCH * KCLS];
__device__ float g_colmax[BATCH * HW];
__device__ float g_colinv[BATCH * HW];

// ---------------------------------------------------------------------------
// Generic GEMM: out[b,k,n] = sum_c A[k,c] * Bm[b,c,n]
//   A: [KCLS, C] row-major, batched with stride aStride (0 => shared across b)
//   Bm: [BATCH, C, HW], out: [BATCH, KCLS, HW]
// Tiles: BM=64 (k), BN=64 (n), BK=16 (c); 256 threads, 4x4 per thread.
// ---------------------------------------------------------------------------
__global__ __launch_bounds__(256) void k_gemm_knc(
    const float* __restrict__ A, long aStride,
    const float* __restrict__ Bm, float* __restrict__ out)
{
    __shared__ float As[16][64];   // [c][k]
    __shared__ float Bs[16][64];   // [c][n]
    const int t = threadIdx.x;
    const int k0 = blockIdx.x * 64;
    const int n0 = blockIdx.y * 64;
    const int b  = blockIdx.z;
    const float* Ab = A + (long)b * aStride;
    const float* Bb = Bm + (long)b * C * HW;

    const int tm = (t >> 4) * 4;
    const int tn = (t & 15) * 4;
    const int arow = t >> 2;          // 0..63 (k within tile)
    const int acol = (t & 3) * 4;     // 0..12 (c within tile)
    const int brow = t >> 4;          // 0..15 (c within tile)
    const int bcol = (t & 15) * 4;    // 0..60 (n within tile)

    float acc[4][4] = {};

    for (int c0 = 0; c0 < C; c0 += 16) {
        float4 av = make_float4(0.f, 0.f, 0.f, 0.f);
        if (k0 + arow < KCLS)
            av = *(const float4*)&Ab[(long)(k0 + arow) * C + c0 + acol];
        As[acol + 0][arow] = av.x;
        As[acol + 1][arow] = av.y;
        As[acol + 2][arow] = av.z;
        As[acol + 3][arow] = av.w;

        *(float4*)&Bs[brow][bcol] =
            *(const float4*)&Bb[(long)(c0 + brow) * HW + n0 + bcol];
        __syncthreads();

        #pragma unroll
        for (int kk = 0; kk < 16; ++kk) {
            float4 a4 = *(const float4*)&As[kk][tm];
            float4 b4 = *(const float4*)&Bs[kk][tn];
            float aa[4] = {a4.x, a4.y, a4.z, a4.w};
            float bb[4] = {b4.x, b4.y, b4.z, b4.w};
            #pragma unroll
            for (int i = 0; i < 4; ++i)
                #pragma unroll
                for (int j = 0; j < 4; ++j)
                    acc[i][j] = fmaf(aa[i], bb[j], acc[i][j]);
        }
        __syncthreads();
    }

    #pragma unroll
    for (int i = 0; i < 4; ++i) {
        int k = k0 + tm + i;
        if (k < KCLS) {
            float4 v = make_float4(acc[i][0], acc[i][1], acc[i][2], acc[i][3]);
            *(float4*)&out[((long)b * KCLS + k) * HW + n0 + tn] = v;
        }
    }
}

// ---------------------------------------------------------------------------
// Row softmax stats over n (per b,k): max + sum(exp)
// ---------------------------------------------------------------------------
__global__ __launch_bounds__(256) void k_rowstats(
    const float* __restrict__ CA, float* __restrict__ rmax, float* __restrict__ rsum)
{
    const int k = blockIdx.x, b = blockIdx.y, t = threadIdx.x;
    const float* row = CA + ((long)b * KCLS + k) * HW;
    __shared__ float red[256];

    float m = -FLT_MAX;
    for (int i = t; i < HW; i += 256) m = fmaxf(m, row[i]);
    red[t] = m; __syncthreads();
    for (int s = 128; s > 0; s >>= 1) {
        if (t < s) red[t] = fmaxf(red[t], red[t + s]);
        __syncthreads();
    }
    m = red[0]; __syncthreads();

    float sum = 0.f;
    for (int i = t; i < HW; i += 256) sum += __expf(row[i] - m);
    red[t] = sum; __syncthreads();
    for (int s = 128; s > 0; s >>= 1) {
        if (t < s) red[t] += red[t + s];
        __syncthreads();
    }
    if (t == 0) { rmax[b * KCLS + k] = m; rsum[b * KCLS + k] = red[0]; }
}

// ---------------------------------------------------------------------------
// Column softmax stats over k (per b,n): online max/sum -> store max and 1/sum
// ---------------------------------------------------------------------------
__global__ __launch_bounds__(256) void k_colstats(
    const float* __restrict__ CA, float* __restrict__ cmax, float* __restrict__ cinv)
{
    const int n = blockIdx.x * 256 + threadIdx.x;
    const int b = blockIdx.y;
    const float* p = CA + (long)b * KCLS * HW + n;
    float m = -FLT_MAX, s = 0.f;
    for (int k = 0; k < KCLS; ++k) {
        float v = p[(long)k * HW];
        if (v > m) { s = s * __expf(m - v) + 1.f; m = v; }
        else       { s += __expf(v - m); }
    }
    cmax[(long)b * HW + n] = m;
    cinv[(long)b * HW + n] = 1.f / s;
}

// ---------------------------------------------------------------------------
// pool[b,k,c] = (1/rowsum) * sum_n exp(CA[b,k,n]-rowmax) * x[b,c,n]
// GEMM M=150(k), N=512(c), Kdim=16384(n)
// ---------------------------------------------------------------------------
__global__ __launch_bounds__(256) void k_clspool(
    const float* __restrict__ CA, const float* __restrict__ X,
    const float* __restrict__ rmax, const float* __restrict__ rsum,
    float* __restrict__ pool)
{
    __shared__ float As[16][64];   // [n][k]
    __shared__ float Bs[16][64];   // [n][c]
    const int t = threadIdx.x;
    const int k0 = blockIdx.x * 64;
    const int c0 = blockIdx.y * 64;
    const int b  = blockIdx.z;
    const float* CAb = CA + (long)b * KCLS * HW;
    const float* Xb  = X  + (long)b * C * HW;

    const int tm = (t >> 4) * 4;
    const int tn = (t & 15) * 4;
    const int arow = t >> 2;       // k within tile (0..63)
    const int acol = (t & 3) * 4;  // n within tile
    const int bc   = t >> 2;       // c within tile (0..63)
    const int bn   = (t & 3) * 4;  // n within tile

    const float rm = (k0 + arow < KCLS) ? rmax[b * KCLS + k0 + arow] : 0.f;
    float acc[4][4] = {};

    for (int n0 = 0; n0 < HW; n0 += 16) {
        float4 av = make_float4(0.f, 0.f, 0.f, 0.f);
        if (k0 + arow < KCLS) {
            av = *(const float4*)&CAb[(long)(k0 + arow) * HW + n0 + acol];
            av.x = __expf(av.x - rm); av.y = __expf(av.y - rm);
            av.z = __expf(av.z - rm); av.w = __expf(av.w - rm);
        }
        As[acol + 0][arow] = av.x;
        As[acol + 1][arow] = av.y;
        As[acol + 2][arow] = av.z;
        As[acol + 3][arow] = av.w;

        float4 bv = *(const float4*)&Xb[(long)(c0 + bc) * HW + n0 + bn];
        Bs[bn + 0][bc] = bv.x;
        Bs[bn + 1][bc] = bv.y;
        Bs[bn + 2][bc] = bv.z;
        Bs[bn + 3][bc] = bv.w;
        __syncthreads();

        #pragma unroll
        for (int kk = 0; kk < 16; ++kk) {
            float4 a4 = *(const float4*)&As[kk][tm];
            float4 b4 = *(const float4*)&Bs[kk][tn];
            float aa[4] = {a4.x, a4.y, a4.z, a4.w};
            float bb[4] = {b4.x, b4.y, b4.z, b4.w};
            #pragma unroll
            for (int i = 0; i < 4; ++i)
                #pragma unroll
                for (int j = 0; j < 4; ++j)
                    acc[i][j] = fmaf(aa[i], bb[j], acc[i][j]);
        }
        __syncthreads();
    }

    #pragma unroll
    for (int i = 0; i < 4; ++i) {
        int k = k0 + tm + i;
        if (k < KCLS) {
            float inv = 1.f / rsum[b * KCLS + k];
            float4 v = make_float4(acc[i][0] * inv, acc[i][1] * inv,
                                   acc[i][2] * inv, acc[i][3] * inv);
            *(float4*)&pool[((long)b * KCLS + k) * C + c0 + tn] = v;
        }
    }
}

// ---------------------------------------------------------------------------
// out[z,k,c] = sum_c' A[z,k,c'] * W[c,c']  (+ addM[k,c] if addM != null)
// ---------------------------------------------------------------------------
__global__ __launch_bounds__(256) void k_linear(
    const float* __restrict__ A, long aStride,
    const float* __restrict__ W, const float* __restrict__ addM,
    float* __restrict__ out)
{
    __shared__ float As[16][64];   // [c'][k]
    __shared__ float Bs[16][64];   // [c'][c]
    const int t = threadIdx.x;
    const int k0 = blockIdx.x * 64;
    const int c0 = blockIdx.y * 64;
    const int z  = blockIdx.z;
    const float* Az = A + (long)z * aStride;

    const int tm = (t >> 4) * 4;
    const int tn = (t & 15) * 4;
    const int arow = t >> 2;
    const int acol = (t & 3) * 4;
    const int bc   = t >> 2;       // c within tile
    const int bp   = (t & 3) * 4;  // c' within tile
    float acc[4][4] = {};

    for (int p0 = 0; p0 < C; p0 += 16) {
        float4 av = make_float4(0.f, 0.f, 0.f, 0.f);
        if (k0 + arow < KCLS)
            av = *(const float4*)&Az[(long)(k0 + arow) * C + p0 + acol];
        As[acol + 0][arow] = av.x;
        As[acol + 1][arow] = av.y;
        As[acol + 2][arow] = av.z;
        As[acol + 3][arow] = av.w;

        float4 bv = *(const float4*)&W[(long)(c0 + bc) * C + p0 + bp];
        Bs[bp + 0][bc] = bv.x;
        Bs[bp + 1][bc] = bv.y;
        Bs[bp + 2][bc] = bv.z;
        Bs[bp + 3][bc] = bv.w;
        __syncthreads();

        #pragma unroll
        for (int kk = 0; kk < 16; ++kk) {
            float4 a4 = *(const float4*)&As[kk][tm];
            float4 b4 = *(const float4*)&Bs[kk][tn];
            float aa[4] = {a4.x, a4.y, a4.z, a4.w};
            float bb[4] = {b4.x, b4.y, b4.z, b4.w};
            #pragma unroll
            for (int i = 0; i < 4; ++i)
                #pragma unroll
                for (int j = 0; j < 4; ++j)
                    acc[i][j] = fmaf(aa[i], bb[j], acc[i][j]);
        }
        __syncthreads();
    }

    #pragma unroll
    for (int i = 0; i < 4; ++i) {
        int k = k0 + tm + i;
        if (k < KCLS) {
            #pragma unroll
            for (int j = 0; j < 4; ++j) {
                float v = acc[i][j];
                if (addM) v += addM[(long)k * C + c0 + tn + j];
                out[((long)z * KCLS + k) * C + c0 + tn + j] = v;
            }
        }
    }
}

// ---------------------------------------------------------------------------
// af[b,c,n] = x[b,c,n] + sum_k pos_attn[b,k,n] * clsWf[k,c]
//   pos_attn = exp(CA - colmax[n]) * colinv[n]
// GEMM M=512(c), N=16384(n), Kdim=150(k)
// ---------------------------------------------------------------------------
__global__ __launch_bounds__(256) void k_alignedfeat(
    const float* __restrict__ CA, const float* __restrict__ Wfc,
    const float* __restrict__ X,
    const float* __restrict__ cmax, const float* __restrict__ cinv,
    float* __restrict__ af)
{
    __shared__ float As[16][64];   // [k][c]
    __shared__ float Bs[16][64];   // [k][n]
    __shared__ float cm_s[64], ci_s[64];
    const int t = threadIdx.x;
    const int c0 = blockIdx.x * 64;
    const int n0 = blockIdx.y * 64;
    const int b  = blockIdx.z;
    const float* CAb = CA + (long)b * KCLS * HW;

    if (t < 64) {
        cm_s[t] = cmax[(long)b * HW + n0 + t];
        ci_s[t] = cinv[(long)b * HW + n0 + t];
    }
    __syncthreads();

    const int tm = (t >> 4) * 4;
    const int tn = (t & 15) * 4;
    const int row = t >> 4;          // k within tile (0..15)
    const int col = (t & 15) * 4;    // c or n within tile
    float acc[4][4] = {};

    for (int kk0 = 0; kk0 < KCLS; kk0 += 16) {
        const int k = kk0 + row;
        float4 av = make_float4(0.f, 0.f, 0.f, 0.f);
        float4 bv = make_float4(0.f, 0.f, 0.f, 0.f);
        if (k < KCLS) {
            av = *(const float4*)&Wfc[(long)k * C + c0 + col];
            bv = *(const float4*)&CAb[(long)k * HW + n0 + col];
            bv.x = __expf(bv.x - cm_s[col + 0]) * ci_s[col + 0];
            bv.y = __expf(bv.y - cm_s[col + 1]) * ci_s[col + 1];
            bv.z = __expf(bv.z - cm_s[col + 2]) * ci_s[col + 2];
            bv.w = __expf(bv.w - cm_s[col + 3]) * ci_s[col + 3];
        }
        *(float4*)&As[row][col] = av;
        *(float4*)&Bs[row][col] = bv;
        __syncthreads();

        #pragma unroll
        for (int kk = 0; kk < 16; ++kk) {
            float4 a4 = *(const float4*)&As[kk][tm];
            float4 b4 = *(const float4*)&Bs[kk][tn];
            float aa[4] = {a4.x, a4.y, a4.z, a4.w};
            float bb[4] = {b4.x, b4.y, b4.z, b4.w};
            #pragma unroll
            for (int i = 0; i < 4; ++i)
                #pragma unroll
                for (int j = 0; j < 4; ++j)
                    acc[i][j] = fmaf(aa[i], bb[j], acc[i][j]);
        }
        __syncthreads();
    }

    #pragma unroll
    for (int i = 0; i < 4; ++i) {
        long idx = ((long)b * C + c0 + tm + i) * HW + n0 + tn;
        float4 xv = *(const float4*)&X[idx];
        float4 v = make_float4(xv.x + acc[i][0], xv.y + acc[i][1],
                               xv.z + acc[i][2], xv.w + acc[i][3]);
        *(float4*)&af[idx] = v;
    }
}

// ---------------------------------------------------------------------------
// LayerNorm over K per (b,n); masks stored [b,k,n]; output same layout.
// ---------------------------------------------------------------------------
__global__ __launch_bounds__(256) void k_layernorm(
    const float* __restrict__ Msk, const float* __restrict__ gamma,
    const float* __restrict__ beta, float* __restrict__ out)
{
    __shared__ float g_s[KCLS], b_s[KCLS];
    const int t = threadIdx.x;
    for (int i = t; i < KCLS; i += 256) { g_s[i] = gamma[i]; b_s[i] = beta[i]; }
    __syncthreads();

    const int n = blockIdx.x * 256 + t;
    const int b = blockIdx.y;
    const float* p = Msk + (long)b * KCLS * HW + n;

    float sum = 0.f, sq = 0.f;
    for (int k = 0; k < KCLS; ++k) {
        float v = p[(long)k * HW];
        sum += v; sq += v * v;
    }
    const float mu  = sum * (1.f / KCLS);
    const float var = sq * (1.f / KCLS) - mu * mu;
    const float rs  = rsqrtf(var + 1e-5f);

    float* o = out + (long)b * KCLS * HW + n;
    for (int k = 0; k < KCLS; ++k) {
        float v = p[(long)k * HW];
        o[(long)k * HW] = (v - mu) * rs * g_s[k] + b_s[k];
    }
}

// ---------------------------------------------------------------------------
extern "C" void kernel_launch(void* const* d_in, const int* in_sizes, int n_in,
                              void* d_out, int out_size)
{
    const float* x     = (const float*)d_in[0];
    const float* cls   = (const float*)d_in[1];
    const float* Wcls  = (const float*)d_in[2];
    const float* Wfeat = (const float*)d_in[3];
    const float* gamma = (const float*)d_in[4];
    const float* beta  = (const float*)d_in[5];
    float* out = (float*)d_out;

    float *CA, *af, *pool, *acls, *clsWf, *rmax, *rsum, *cmax, *cinv;
    cudaGetSymbolAddress((void**)&CA,    g_CA);
    cudaGetSymbolAddress((void**)&af,    g_af);
    cudaGetSymbolAddress((void**)&pool,  g_pool);
    cudaGetSymbolAddress((void**)&acls,  g_acls);
    cudaGetSymbolAddress((void**)&clsWf, g_clsWf);
    cudaGetSymbolAddress((void**)&rmax,  g_rowmax);
    cudaGetSymbolAddress((void**)&rsum,  g_rowsum);
    cudaGetSymbolAddress((void**)&cmax,  g_colmax);
    cudaGetSymbolAddress((void**)&cinv,  g_colinv);

    // 1. coupled_attn = cls @ x  -> CA [b,150,16384]
    k_gemm_knc<<<dim3(3, 256, BATCH), 256>>>(cls, 0, x, CA);
    // 2. softmax stats
    k_rowstats<<<dim3(KCLS, BATCH), 256>>>(CA, rmax, rsum);
    k_colstats<<<dim3(HW / 256, BATCH), 256>>>(CA, cmax, cinv);
    // 3. cls pooling GEMM
    k_clspool<<<dim3(3, C / 64, BATCH), 256>>>(CA, x, rmax, rsum, pool);
    // 4. clsWf = cls @ W_feat^T (shared), aligned_cls = cls + pool @ W_cls^T
    k_linear<<<dim3(3, C / 64, 1), 256>>>(cls, 0, Wfeat, nullptr, clsWf);
    k_linear<<<dim3(3, C / 64, BATCH), 256>>>(pool, (long)KCLS * C, Wcls, cls, acls);
    // 5. aligned_feat (transposed [b,c,n])
    k_alignedfeat<<<dim3(C / 64, HW / 64, BATCH), 256>>>(CA, clsWf, x, cmax, cinv, af);
    // 6. masks = acls @ af -> reuse CA buffer, layout [b,k,n]
    k_gemm_knc<<<dim3(3, 256, BATCH), 256>>>(acls, (long)KCLS * C, af, CA);
    // 7. LayerNorm over K + write output [b,K,h,w]
    k_layernorm<<<dim3(HW / 256, BATCH), 256>>>(CA, gamma, beta, out);
}

// round 2
// speedup vs baseline: 1.3774x; 1.3774x over previous
#include <cuda_runtime.h>
#include <float.h>

#define BATCH 8
#define C 512
#define HW 16384
#define KCLS 150
#define KPAD 160
#define NSPLIT 8

// ---------------- scratch (device globals; no allocations) ----------------
__device__ float g_E[BATCH * KCLS * HW];        // exp(coupled_attn)
__device__ float g_colinv[BATCH * HW];          // 1 / sum_k E
__device__ float g_rowpart[BATCH * KPAD * 256]; // per-n-tile partial row sums
__device__ float g_rinv[BATCH * KPAD];          // 1 / sum_n E
__device__ float g_poolpart[NSPLIT * BATCH * KPAD * C];
__device__ float g_acls[BATCH * KCLS * C];
__device__ float g_clsWf[KCLS * C];             // cls @ W_feat^T
__device__ float g_G[BATCH * KPAD * KPAD];      // acls @ clsWf^T (zero padded)

// ===========================================================================
// GEMM1: E[b,k,n] = exp( sum_c cls[k,c] * x[b,c,n] )
// Tile: BM=160 (all k), BN=64 (n), BK=32. 256 thr, 5x8 micro.
// Epilogue: colinv[b,n] (full, in-block) + rowpart[b,k,ntile].
// ===========================================================================
__global__ __launch_bounds__(256) void k_gemm1(
    const float* __restrict__ cls, const float* __restrict__ x,
    float* __restrict__ E, float* __restrict__ colinv, float* __restrict__ rowpart)
{
    __shared__ float As[32][161];   // [c][k]
    __shared__ float Bs[32][64];    // [c][n]
    const int t  = threadIdx.x;
    const int n0 = blockIdx.x * 64;
    const int b  = blockIdx.y;
    const int rt = t >> 3, ct = t & 7;
    const float* Xb = x + (long)b * C * HW;

    float acc[5][8] = {};
    for (int c0 = 0; c0 < C; c0 += 32) {
        #pragma unroll
        for (int i = 0; i < 5; ++i) {
            int f = t + 256 * i, row = f >> 3, c4 = (f & 7) * 4;
            float4 v = make_float4(0.f, 0.f, 0.f, 0.f);
            if (row < KCLS) v = *(const float4*)&cls[(long)row * C + c0 + c4];
            As[c4 + 0][row] = v.x; As[c4 + 1][row] = v.y;
            As[c4 + 2][row] = v.z; As[c4 + 3][row] = v.w;
        }
        #pragma unroll
        for (int i = 0; i < 2; ++i) {
            int f = t + 256 * i, r = f >> 4, c4 = (f & 15) * 4;
            *(float4*)&Bs[r][c4] = *(const float4*)&Xb[(long)(c0 + r) * HW + n0 + c4];
        }
        __syncthreads();
        #pragma unroll 8
        for (int kk = 0; kk < 32; ++kk) {
            float aa[5];
            #pragma unroll
            for (int i = 0; i < 5; ++i) aa[i] = As[kk][rt + 32 * i];
            float4 b0 = *(const float4*)&Bs[kk][ct * 8];
            float4 b1 = *(const float4*)&Bs[kk][ct * 8 + 4];
            float bb[8] = {b0.x, b0.y, b0.z, b0.w, b1.x, b1.y, b1.z, b1.w};
            #pragma unroll
            for (int i = 0; i < 5; ++i)
                #pragma unroll
                for (int j = 0; j < 8; ++j)
                    acc[i][j] = fmaf(aa[i], bb[j], acc[i][j]);
        }
        __syncthreads();
    }

    #pragma unroll
    for (int i = 0; i < 5; ++i)
        #pragma unroll
        for (int j = 0; j < 8; ++j)
            acc[i][j] = __expf(acc[i][j]);

    // store E rows < KCLS
    #pragma unroll
    for (int i = 0; i < 5; ++i) {
        int m = rt + 32 * i;
        if (m < KCLS) {
            long base = ((long)b * KCLS + m) * HW + n0 + ct * 8;
            *(float4*)&E[base]     = make_float4(acc[i][0], acc[i][1], acc[i][2], acc[i][3]);
            *(float4*)&E[base + 4] = make_float4(acc[i][4], acc[i][5], acc[i][6], acc[i][7]);
        }
    }

    // epilogue sums (reuse smem)
    float* S  = &As[0][0];   // 32x64 column partials
    float* Rd = &Bs[0][0];   // 160x8 row partials
    float cs[8] = {};
    #pragma unroll
    for (int i = 0; i < 5; ++i) {
        int m = rt + 32 * i;
        float rsum = 0.f;
        #pragma unroll
        for (int j = 0; j < 8; ++j) {
            float v = acc[i][j];
            rsum += v;
            if (m < KCLS) cs[j] += v;
        }
        Rd[m * 8 + ct] = rsum;
    }
    #pragma unroll
    for (int j = 0; j < 8; ++j) S[rt * 64 + ct * 8 + j] = cs[j];
    __syncthreads();
    if (t < 64) {
        float s = 0.f;
        for (int r = 0; r < 32; ++r) s += S[r * 64 + t];
        colinv[(long)b * HW + n0 + t] = 1.f / s;
    }
    if (t < KPAD) {
        float s = 0.f;
        #pragma unroll
        for (int c = 0; c < 8; ++c) s += Rd[t * 8 + c];
        rowpart[((long)b * KPAD + t) * 256 + blockIdx.x] = s;
    }
}

// ===========================================================================
__global__ void k_rowred(const float* __restrict__ rowpart, float* __restrict__ rinv)
{
    int idx = blockIdx.x * 256 + threadIdx.x;
    if (idx < BATCH * KPAD) {
        const float* p = rowpart + (long)idx * 256;
        float s = 0.f;
        for (int i = 0; i < 256; ++i) s += p[i];
        rinv[idx] = 1.f / s;
    }
}

// ===========================================================================
// clspool: poolpart[sp,b,k,c] = sum_{n in split} E[b,k,n] * x[b,c,n]
// Tile: BM=160(k) x BN=64(c), BK=32 over n.
// ===========================================================================
__global__ __launch_bounds__(256) void k_clspool(
    const float* __restrict__ E, const float* __restrict__ x,
    float* __restrict__ poolpart)
{
    __shared__ float As[32][161];   // [n][k]
    __shared__ float Bs[32][68];    // [n][c]  (padded rows, 16B aligned)
    const int t  = threadIdx.x;
    const int c0 = blockIdx.x * 64;
    const int sp = blockIdx.y;
    const int b  = blockIdx.z;
    const int rt = t >> 3, ct = t & 7;
    const float* Eb = E + (long)b * KCLS * HW;
    const float* Xb = x + (long)b * C * HW;
    const int nbase0 = sp * (HW / NSPLIT);

    float acc[5][8] = {};
    for (int nn = 0; nn < HW / NSPLIT; nn += 32) {
        const int nb = nbase0 + nn;
        #pragma unroll
        for (int i = 0; i < 5; ++i) {
            int f = t + 256 * i, row = f >> 3, c4 = (f & 7) * 4;
            float4 v = make_float4(0.f, 0.f, 0.f, 0.f);
            if (row < KCLS) v = *(const float4*)&Eb[(long)row * HW + nb + c4];
            As[c4 + 0][row] = v.x; As[c4 + 1][row] = v.y;
            As[c4 + 2][row] = v.z; As[c4 + 3][row] = v.w;
        }
        #pragma unroll
        for (int i = 0; i < 2; ++i) {
            int f = t + 256 * i, r = f >> 3, c4 = (f & 7) * 4;
            float4 v = *(const float4*)&Xb[(long)(c0 + r) * HW + nb + c4];
            Bs[c4 + 0][r] = v.x; Bs[c4 + 1][r] = v.y;
            Bs[c4 + 2][r] = v.z; Bs[c4 + 3][r] = v.w;
        }
        __syncthreads();
        #pragma unroll 8
        for (int kk = 0; kk < 32; ++kk) {
            float aa[5];
            #pragma unroll
            for (int i = 0; i < 5; ++i) aa[i] = As[kk][rt + 32 * i];
            float4 b0 = *(const float4*)&Bs[kk][ct * 8];
            float4 b1 = *(const float4*)&Bs[kk][ct * 8 + 4];
            float bb[8] = {b0.x, b0.y, b0.z, b0.w, b1.x, b1.y, b1.z, b1.w};
            #pragma unroll
            for (int i = 0; i < 5; ++i)
                #pragma unroll
                for (int j = 0; j < 8; ++j)
                    acc[i][j] = fmaf(aa[i], bb[j], acc[i][j]);
        }
        __syncthreads();
    }
    #pragma unroll
    for (int i = 0; i < 5; ++i) {
        int m = rt + 32 * i;
        long base = (((long)sp * BATCH + b) * KPAD + m) * C + c0 + ct * 8;
        *(float4*)&poolpart[base]     = make_float4(acc[i][0], acc[i][1], acc[i][2], acc[i][3]);
        *(float4*)&poolpart[base + 4] = make_float4(acc[i][4], acc[i][5], acc[i][6], acc[i][7]);
    }
}

// ===========================================================================
// Small linear: out[k,c] = sum_p A[k,p] * W[c,p]   (clsWf = cls @ Wfeat^T)
// ===========================================================================
__global__ __launch_bounds__(256) void k_clsWf(
    const float* __restrict__ A, const float* __restrict__ W,
    float* __restrict__ out)
{
    __shared__ float As[16][64];
    __shared__ float Bs[16][64];
    const int t = threadIdx.x;
    const int k0 = blockIdx.x * 64, c0 = blockIdx.y * 64;
    const int tm = (t >> 4) * 4, tn = (t & 15) * 4;
    const int arow = t >> 2, acol = (t & 3) * 4;
    const int bc = t >> 2, bp = (t & 3) * 4;
    float acc[4][4] = {};

    for (int p0 = 0; p0 < C; p0 += 16) {
        float4 av = make_float4(0.f, 0.f, 0.f, 0.f);
        if (k0 + arow < KCLS)
            av = *(const float4*)&A[(long)(k0 + arow) * C + p0 + acol];
        As[acol + 0][arow] = av.x; As[acol + 1][arow] = av.y;
        As[acol + 2][arow] = av.z; As[acol + 3][arow] = av.w;
        float4 bv = *(const float4*)&W[(long)(c0 + bc) * C + p0 + bp];
        Bs[bp + 0][bc] = bv.x; Bs[bp + 1][bc] = bv.y;
        Bs[bp + 2][bc] = bv.z; Bs[bp + 3][bc] = bv.w;
        __syncthreads();
        #pragma unroll
        for (int kk = 0; kk < 16; ++kk) {
            float4 a4 = *(const float4*)&As[kk][tm];
            float4 b4 = *(const float4*)&Bs[kk][tn];
            float aa[4] = {a4.x, a4.y, a4.z, a4.w};
            float bb[4] = {b4.x, b4.y, b4.z, b4.w};
            #pragma unroll
            for (int i = 0; i < 4; ++i)
                #pragma unroll
                for (int j = 0; j < 4; ++j)
                    acc[i][j] = fmaf(aa[i], bb[j], acc[i][j]);
        }
        __syncthreads();
    }
    #pragma unroll
    for (int i = 0; i < 4; ++i) {
        int k = k0 + tm + i;
        if (k < KCLS)
            *(float4*)&out[(long)k * C + c0 + tn] =
                make_float4(acc[i][0], acc[i][1], acc[i][2], acc[i][3]);
    }
}

// ===========================================================================
// acls[b,k,c] = cls[k,c] + rinv[b,k] * (sum_s poolpart) @ Wcls^T
// ===========================================================================
__global__ __launch_bounds__(256) void k_acls(
    const float* __restrict__ poolpart, const float* __restrict__ rinv,
    const float* __restrict__ W, const float* __restrict__ cls,
    float* __restrict__ out)
{
    __shared__ float As[16][64];
    __shared__ float Bs[16][64];
    const int t = threadIdx.x;
    const int k0 = blockIdx.x * 64, c0 = blockIdx.y * 64, b = blockIdx.z;
    const int tm = (t >> 4) * 4, tn = (t & 15) * 4;
    const int arow = t >> 2, acol = (t & 3) * 4;
    const int bc = t >> 2, bp = (t & 3) * 4;
    float acc[4][4] = {};
    const int ka = k0 + arow;
    const float rv = (ka < KCLS) ? rinv[b * KPAD + ka] : 0.f;

    for (int p0 = 0; p0 < C; p0 += 16) {
        float4 av = make_float4(0.f, 0.f, 0.f, 0.f);
        if (ka < KCLS) {
            #pragma unroll
            for (int s = 0; s < NSPLIT; ++s) {
                float4 v = *(const float4*)
                    &poolpart[(((long)s * BATCH + b) * KPAD + ka) * C + p0 + acol];
                av.x += v.x; av.y += v.y; av.z += v.z; av.w += v.w;
            }
            av.x *= rv; av.y *= rv; av.z *= rv; av.w *= rv;
        }
        As[acol + 0][arow] = av.x; As[acol + 1][arow] = av.y;
        As[acol + 2][arow] = av.z; As[acol + 3][arow] = av.w;
        float4 bv = *(const float4*)&W[(long)(c0 + bc) * C + p0 + bp];
        Bs[bp + 0][bc] = bv.x; Bs[bp + 1][bc] = bv.y;
        Bs[bp + 2][bc] = bv.z; Bs[bp + 3][bc] = bv.w;
        __syncthreads();
        #pragma unroll
        for (int kk = 0; kk < 16; ++kk) {
            float4 a4 = *(const float4*)&As[kk][tm];
            float4 b4 = *(const float4*)&Bs[kk][tn];
            float aa[4] = {a4.x, a4.y, a4.z, a4.w};
            float bb[4] = {b4.x, b4.y, b4.z, b4.w};
            #pragma unroll
            for (int i = 0; i < 4; ++i)
                #pragma unroll
                for (int j = 0; j < 4; ++j)
                    acc[i][j] = fmaf(aa[i], bb[j], acc[i][j]);
        }
        __syncthreads();
    }
    #pragma unroll
    for (int i = 0; i < 4; ++i) {
        int k = k0 + tm + i;
        if (k < KCLS) {
            #pragma unroll
            for (int j = 0; j < 4; ++j)
                out[((long)b * KCLS + k) * C + c0 + tn + j] =
                    acc[i][j] + cls[(long)k * C + c0 + tn + j];
        }
    }
}

// ===========================================================================
// G[b,k,k2] = sum_p acls[b,k,p] * clsWf[k2,p]    (zero-padded to 160x160)
// ===========================================================================
__global__ __launch_bounds__(256) void k_G(
    const float* __restrict__ acls, const float* __restrict__ clsWf,
    float* __restrict__ G)
{
    __shared__ float As[16][64];
    __shared__ float Bs[16][64];
    const int t = threadIdx.x;
    const int k0 = blockIdx.x * 64, k20 = blockIdx.y * 64, b = blockIdx.z;
    const int tm = (t >> 4) * 4, tn = (t & 15) * 4;
    const int arow = t >> 2, acol = (t & 3) * 4;
    const int bc = t >> 2, bp = (t & 3) * 4;
    float acc[4][4] = {};

    for (int p0 = 0; p0 < C; p0 += 16) {
        float4 av = make_float4(0.f, 0.f, 0.f, 0.f);
        if (k0 + arow < KCLS)
            av = *(const float4*)&acls[((long)b * KCLS + k0 + arow) * C + p0 + acol];
        As[acol + 0][arow] = av.x; As[acol + 1][arow] = av.y;
        As[acol + 2][arow] = av.z; As[acol + 3][arow] = av.w;
        float4 bv = make_float4(0.f, 0.f, 0.f, 0.f);
        if (k20 + bc < KCLS)
            bv = *(const float4*)&clsWf[(long)(k20 + bc) * C + p0 + bp];
        Bs[bp + 0][bc] = bv.x; Bs[bp + 1][bc] = bv.y;
        Bs[bp + 2][bc] = bv.z; Bs[bp + 3][bc] = bv.w;
        __syncthreads();
        #pragma unroll
        for (int kk = 0; kk < 16; ++kk) {
            float4 a4 = *(const float4*)&As[kk][tm];
            float4 b4 = *(const float4*)&Bs[kk][tn];
            float aa[4] = {a4.x, a4.y, a4.z, a4.w};
            float bb[4] = {b4.x, b4.y, b4.z, b4.w};
            #pragma unroll
            for (int i = 0; i < 4; ++i)
                #pragma unroll
                for (int j = 0; j < 4; ++j)
                    acc[i][j] = fmaf(aa[i], bb[j], acc[i][j]);
        }
        __syncthreads();
    }
    #pragma unroll
    for (int i = 0; i < 4; ++i) {
        int k = k0 + tm + i;
        if (k < KPAD && k20 + tn < KPAD)
            *(float4*)&G[((long)b * KPAD + k) * KPAD + k20 + tn] =
                make_float4(acc[i][0], acc[i][1], acc[i][2], acc[i][3]);
    }
}

// ===========================================================================
// masksLN: masks[k,n] = sum_c acls[k,c]*x[c,n] + sum_k' G[k,k']*(E[k',n]*colinv[n])
// then LayerNorm over k (150), write out [b,K,h,w].
// Tile: BM=160 (all k) x BN=64 (n).
// ===========================================================================
__global__ __launch_bounds__(256) void k_masksLN(
    const float* __restrict__ acls, const float* __restrict__ x,
    const float* __restrict__ G, const float* __restrict__ E,
    const float* __restrict__ colinv,
    const float* __restrict__ gamma, const float* __restrict__ beta,
    float* __restrict__ out)
{
    __shared__ float As[32][161];
    __shared__ float Bs[32][64];
    __shared__ float cinv_s[64], mean_s[64], rs_s[64];
    __shared__ float gam_s[KCLS], bet_s[KCLS];
    const int t  = threadIdx.x;
    const int n0 = blockIdx.x * 64;
    const int b  = blockIdx.y;
    const int rt = t >> 3, ct = t & 7;
    const float* Xb = x + (long)b * C * HW;

    if (t < 64) cinv_s[t] = colinv[(long)b * HW + n0 + t];
    if (t < KCLS) { gam_s[t] = gamma[t]; bet_s[t] = beta[t]; }
    __syncthreads();

    float acc[5][8] = {};

    // phase 1: reduction over c with A = acls, B = x
    for (int c0 = 0; c0 < C; c0 += 32) {
        #pragma unroll
        for (int i = 0; i < 5; ++i) {
            int f = t + 256 * i, row = f >> 3, c4 = (f & 7) * 4;
            float4 v = make_float4(0.f, 0.f, 0.f, 0.f);
            if (row < KCLS)
                v = *(const float4*)&acls[((long)b * KCLS + row) * C + c0 + c4];
            As[c4 + 0][row] = v.x; As[c4 + 1][row] = v.y;
            As[c4 + 2][row] = v.z; As[c4 + 3][row] = v.w;
        }
        #pragma unroll
        for (int i = 0; i < 2; ++i) {
            int f = t + 256 * i, r = f >> 4, c4 = (f & 15) * 4;
            *(float4*)&Bs[r][c4] = *(const float4*)&Xb[(long)(c0 + r) * HW + n0 + c4];
        }
        __syncthreads();
        #pragma unroll 8
        for (int kk = 0; kk < 32; ++kk) {
            float aa[5];
            #pragma unroll
            for (int i = 0; i < 5; ++i) aa[i] = As[kk][rt + 32 * i];
            float4 b0 = *(const float4*)&Bs[kk][ct * 8];
            float4 b1 = *(const float4*)&Bs[kk][ct * 8 + 4];
            float bb[8] = {b0.x, b0.y, b0.z, b0.w, b1.x, b1.y, b1.z, b1.w};
            #pragma unroll
            for (int i = 0; i < 5; ++i)
                #pragma unroll
                for (int j = 0; j < 8; ++j)
                    acc[i][j] = fmaf(aa[i], bb[j], acc[i][j]);
        }
        __syncthreads();
    }

    // phase 2: reduction over k' with A = G, B = E * colinv
    for (int kp0 = 0; kp0 < KPAD; kp0 += 32) {
        #pragma unroll
        for (int i = 0; i < 5; ++i) {
            int f = t + 256 * i, row = f >> 3, c4 = (f & 7) * 4;
            float4 v = *(const float4*)&G[((long)b * KPAD + row) * KPAD + kp0 + c4];
            As[c4 + 0][row] = v.x; As[c4 + 1][row] = v.y;
            As[c4 + 2][row] = v.z; As[c4 + 3][row] = v.w;
        }
        #pragma unroll
        for (int i = 0; i < 2; ++i) {
            int f = t + 256 * i, r = f >> 4, c4 = (f & 15) * 4;
            float4 v = make_float4(0.f, 0.f, 0.f, 0.f);
            if (kp0 + r < KCLS)
                v = *(const float4*)&E[((long)b * KCLS + kp0 + r) * HW + n0 + c4];
            v.x *= cinv_s[c4 + 0]; v.y *= cinv_s[c4 + 1];
            v.z *= cinv_s[c4 + 2]; v.w *= cinv_s[c4 + 3];
            *(float4*)&Bs[r][c4] = v;
        }
        __syncthreads();
        #pragma unroll 8
        for (int kk = 0; kk < 32; ++kk) {
            float aa[5];
            #pragma unroll
            for (int i = 0; i < 5; ++i) aa[i] = As[kk][rt + 32 * i];
            float4 b0 = *(const float4*)&Bs[kk][ct * 8];
            float4 b1 = *(const float4*)&Bs[kk][ct * 8 + 4];
            float bb[8] = {b0.x, b0.y, b0.z, b0.w, b1.x, b1.y, b1.z, b1.w};
            #pragma unroll
            for (int i = 0; i < 5; ++i)
                #pragma unroll
                for (int j = 0; j < 8; ++j)
                    acc[i][j] = fmaf(aa[i], bb[j], acc[i][j]);
        }
        __syncthreads();
    }

    // LayerNorm over k (150 valid rows) per column
    float* S1 = &As[0][0];
    float* S2 = &Bs[0][0];
    float ls[8] = {}, lq[8] = {};
    #pragma unroll
    for (int i = 0; i < 5; ++i) {
        int m = rt + 32 * i;
        if (m < KCLS) {
            #pragma unroll
            for (int j = 0; j < 8; ++j) {
                float v = acc[i][j];
                ls[j] += v; lq[j] += v * v;
            }
        }
    }
    #pragma unroll
    for (int j = 0; j < 8; ++j) {
        S1[rt * 64 + ct * 8 + j] = ls[j];
        S2[rt * 64 + ct * 8 + j] = lq[j];
    }
    __syncthreads();
    if (t < 64) {
        float s = 0.f, q = 0.f;
        for (int r = 0; r < 32; ++r) { s += S1[r * 64 + t]; q += S2[r * 64 + t]; }
        float mu  = s * (1.f / KCLS);
        float var = q * (1.f / KCLS) - mu * mu;
        mean_s[t] = mu;
        rs_s[t]   = rsqrtf(var + 1e-5f);
    }
    __syncthreads();
    #pragma unroll
    for (int i = 0; i < 5; ++i) {
        int m = rt + 32 * i;
        if (m < KCLS) {
            float g = gam_s[m], be = bet_s[m];
            float o[8];
            #pragma unroll
            for (int j = 0; j < 8; ++j) {
                int col = ct * 8 + j;
                o[j] = (acc[i][j] - mean_s[col]) * rs_s[col] * g + be;
            }
            long base = ((long)b * KCLS + m) * HW + n0 + ct * 8;
            *(float4*)&out[base]     = make_float4(o[0], o[1], o[2], o[3]);
            *(float4*)&out[base + 4] = make_float4(o[4], o[5], o[6], o[7]);
        }
    }
}

// ===========================================================================
extern "C" void kernel_launch(void* const* d_in, const int* in_sizes, int n_in,
                              void* d_out, int out_size)
{
    const float* x     = (const float*)d_in[0];
    const float* cls   = (const float*)d_in[1];
    const float* Wcls  = (const float*)d_in[2];
    const float* Wfeat = (const float*)d_in[3];
    const float* gamma = (const float*)d_in[4];
    const float* beta  = (const float*)d_in[5];
    float* out = (float*)d_out;

    float *E, *colinv, *rowpart, *rinv, *poolpart, *acls, *clsWf, *G;
    cudaGetSymbolAddress((void**)&E,        g_E);
    cudaGetSymbolAddress((void**)&colinv,   g_colinv);
    cudaGetSymbolAddress((void**)&rowpart,  g_rowpart);
    cudaGetSymbolAddress((void**)&rinv,     g_rinv);
    cudaGetSymbolAddress((void**)&poolpart, g_poolpart);
    cudaGetSymbolAddress((void**)&acls,     g_acls);
    cudaGetSymbolAddress((void**)&clsWf,    g_clsWf);
    cudaGetSymbolAddress((void**)&G,        g_G);

    // 1. E = exp(cls @ x), colinv, row partials
    k_gemm1<<<dim3(HW / 64, BATCH), 256>>>(cls, x, E, colinv, rowpart);
    // 2. row-sum reduce -> rinv
    k_rowred<<<(BATCH * KPAD + 255) / 256, 256>>>(rowpart, rinv);
    // 3. pooling partials
    k_clspool<<<dim3(C / 64, NSPLIT, BATCH), 256>>>(E, x, poolpart);
    // 4. clsWf = cls @ Wfeat^T
    k_clsWf<<<dim3(3, C / 64), 256>>>(cls, Wfeat, clsWf);
    // 5. acls = cls + rinv * (sum poolpart) @ Wcls^T
    k_acls<<<dim3(3, C / 64, BATCH), 256>>>(poolpart, rinv, Wcls, cls, acls);
    // 6. G = acls @ clsWf^T (padded 160x160)
    k_G<<<dim3(3, 3, BATCH), 256>>>(acls, clsWf, G);
    // 7. masks + LayerNorm + output
    k_masksLN<<<dim3(HW / 64, BATCH), 256>>>(acls, x, G, E, colinv, gamma, beta, out);
}